// round 3
// baseline (speedup 1.0000x reference)
#include <cuda_runtime.h>
#include <cuda_bf16.h>

// ---------------------------------------------------------------------------
// PSAttention (B=32, CIN=2048, COUT=HW=1024)
//   Y1 = Wr @ X_b + br                      [1024 x 1024] per batch, K=2048
//   C  = softmax_rows( Wc @ Y1 + bc )       softmax over hw (last axis)
//   D  = softmax_cols( Wd @ Y1 + bd )       softmax over channel axis
//   out = Y1 + C @ D^T                      per batch, K=1024
// All fp32.  GEMMs use packed fma.rn.f32x2 (Blackwell FFMA2, 2x fp32 rate).
// ---------------------------------------------------------------------------

#define NB   32
#define MM   1024
#define NN   1024
#define ELEM_PER_B (1024 * 1024)

// Scratch: 3 x 128 MB device globals (no cudaMalloc allowed).
__device__ float g_Y1[NB * ELEM_PER_B];
__device__ float g_C [NB * ELEM_PER_B];
__device__ float g_D [NB * ELEM_PER_B];

// ---- f32x2 helpers --------------------------------------------------------
__device__ __forceinline__ unsigned long long pack_dup(float a) {
    unsigned long long r;
    asm("mov.b64 %0, {%1, %1};" : "=l"(r) : "f"(a));
    return r;
}
__device__ __forceinline__ void fma2(unsigned long long& d,
                                     unsigned long long a,
                                     unsigned long long b) {
    asm("fma.rn.f32x2 %0, %1, %2, %0;" : "+l"(d) : "l"(a), "l"(b));
}
union U64F2 { unsigned long long u; float2 f; };

// ---------------------------------------------------------------------------
// Generic fp32 GEMM: C[M,N] = A[M,K] * B (+bias[m]) (+addend[m,n])
//   TRANSB=false : B is [K,N] row-major (element B[k*N + n])
//   TRANSB=true  : B is [N,K] row-major (element B[n*K + k])  -> C = A * B^T
// Tile 128x128x16, 256 threads, 8x8 per thread, f32x2 accumulators.
// ---------------------------------------------------------------------------
template<bool TRANSB, bool BIAS, bool ADDEND>
__global__ __launch_bounds__(256, 2)
void gemm_f32(const float* __restrict__ A, long strideA,
              const float* __restrict__ B, long strideB,
              const float* __restrict__ bias,
              const float* __restrict__ addend,
              float* __restrict__ C,
              int M, int N, int K)
{
    __shared__ float As[16][128];
    __shared__ float Bs[16][128];

    const int tid  = threadIdx.x;      // 0..255
    const int tx   = tid & 15;         // n-tile lane
    const int ty   = tid >> 4;         // m-tile lane
    const int bz   = blockIdx.z;
    const int row0 = blockIdx.y * 128;
    const int col0 = blockIdx.x * 128;

    const float* Ab = A + (long)bz * strideA;
    const float* Bb = B + (long)bz * strideB;
    float*       Cb = C + (long)bz * (long)M * N;

    // A / B(T) loader: 128 rows x 16 cols, float4 along K, 2 passes
    const int aRow = tid >> 2;         // 0..63
    const int aCol = (tid & 3) << 2;   // 0,4,8,12
    // B(N) loader: 16 rows x 128 cols, float4 along N, 2 passes
    const int bRow = tid >> 5;         // 0..7
    const int bCol = (tid & 31) << 2;  // 0..124

    unsigned long long acc[8][4];
#pragma unroll
    for (int i = 0; i < 8; i++)
#pragma unroll
        for (int j = 0; j < 4; j++) acc[i][j] = 0ULL;

    const int numT = K >> 4;
    float4 pa[2], pb[2];

    // prefetch of one K-tile into registers
    auto load_global = [&](int k0) {
        pa[0] = *(const float4*)&Ab[(long)(row0 + aRow     ) * K + k0 + aCol];
        pa[1] = *(const float4*)&Ab[(long)(row0 + aRow + 64) * K + k0 + aCol];
        if (TRANSB) {
            pb[0] = *(const float4*)&Bb[(long)(col0 + aRow     ) * K + k0 + aCol];
            pb[1] = *(const float4*)&Bb[(long)(col0 + aRow + 64) * K + k0 + aCol];
        } else {
            pb[0] = *(const float4*)&Bb[(long)(k0 + bRow    ) * N + col0 + bCol];
            pb[1] = *(const float4*)&Bb[(long)(k0 + bRow + 8) * N + col0 + bCol];
        }
    };
    auto store_smem = [&]() {
        As[aCol + 0][aRow] = pa[0].x;  As[aCol + 1][aRow] = pa[0].y;
        As[aCol + 2][aRow] = pa[0].z;  As[aCol + 3][aRow] = pa[0].w;
        As[aCol + 0][aRow + 64] = pa[1].x;  As[aCol + 1][aRow + 64] = pa[1].y;
        As[aCol + 2][aRow + 64] = pa[1].z;  As[aCol + 3][aRow + 64] = pa[1].w;
        if (TRANSB) {
            Bs[aCol + 0][aRow] = pb[0].x;  Bs[aCol + 1][aRow] = pb[0].y;
            Bs[aCol + 2][aRow] = pb[0].z;  Bs[aCol + 3][aRow] = pb[0].w;
            Bs[aCol + 0][aRow + 64] = pb[1].x;  Bs[aCol + 1][aRow + 64] = pb[1].y;
            Bs[aCol + 2][aRow + 64] = pb[1].z;  Bs[aCol + 3][aRow + 64] = pb[1].w;
        } else {
            *(float4*)&Bs[bRow    ][bCol] = pb[0];
            *(float4*)&Bs[bRow + 8][bCol] = pb[1];
        }
    };

    load_global(0);
    store_smem();
    __syncthreads();

    for (int t = 0; t < numT; t++) {
        if (t + 1 < numT) load_global((t + 1) << 4);

#pragma unroll
        for (int k = 0; k < 16; k++) {
            float4 a0 = *(const float4*)&As[k][ty * 8];
            float4 a1 = *(const float4*)&As[k][ty * 8 + 4];
            const unsigned long long* bsp =
                (const unsigned long long*)&Bs[k][tx * 8];
            unsigned long long bp0 = bsp[0], bp1 = bsp[1];
            unsigned long long bp2 = bsp[2], bp3 = bsp[3];
            float av[8] = {a0.x, a0.y, a0.z, a0.w, a1.x, a1.y, a1.z, a1.w};
#pragma unroll
            for (int i = 0; i < 8; i++) {
                unsigned long long ap = pack_dup(av[i]);
                fma2(acc[i][0], ap, bp0);
                fma2(acc[i][1], ap, bp1);
                fma2(acc[i][2], ap, bp2);
                fma2(acc[i][3], ap, bp3);
            }
        }
        __syncthreads();
        if (t + 1 < numT) store_smem();
        __syncthreads();
    }

    // epilogue
    const float* ad = ADDEND ? (addend + (long)bz * (long)M * N) : nullptr;
#pragma unroll
    for (int i = 0; i < 8; i++) {
        int  row  = row0 + ty * 8 + i;
        float bv  = BIAS ? __ldg(&bias[row]) : 0.0f;
        long base = (long)row * N + col0 + tx * 8;
#pragma unroll
        for (int j = 0; j < 4; j++) {
            U64F2 cv; cv.u = acc[i][j];
            float r0 = cv.f.x + bv;
            float r1 = cv.f.y + bv;
            if (ADDEND) {
                r0 += ad[base + 2 * j];
                r1 += ad[base + 2 * j + 1];
            }
            float2 o; o.x = r0; o.y = r1;
            *(float2*)&Cb[base + 2 * j] = o;
        }
    }
}

// ---------------------------------------------------------------------------
// Row softmax over last axis (length 1024). One block per (b, c) row.
// ---------------------------------------------------------------------------
__global__ void row_softmax_kernel(float* __restrict__ data)
{
    long row = blockIdx.x;
    float4* p = reinterpret_cast<float4*>(data + row * 1024);
    int t = threadIdx.x;               // 256 threads, 4 floats each

    float4 v = p[t];
    float m = fmaxf(fmaxf(v.x, v.y), fmaxf(v.z, v.w));

    __shared__ float red[256];
    red[t] = m;
    __syncthreads();
    for (int s = 128; s > 0; s >>= 1) {
        if (t < s) red[t] = fmaxf(red[t], red[t + s]);
        __syncthreads();
    }
    m = red[0];
    __syncthreads();

    float4 e;
    e.x = __expf(v.x - m); e.y = __expf(v.y - m);
    e.z = __expf(v.z - m); e.w = __expf(v.w - m);
    float s4 = e.x + e.y + e.z + e.w;

    red[t] = s4;
    __syncthreads();
    for (int s = 128; s > 0; s >>= 1) {
        if (t < s) red[t] += red[t + s];
        __syncthreads();
    }
    float inv = 1.0f / red[0];

    e.x *= inv; e.y *= inv; e.z *= inv; e.w *= inv;
    p[t] = e;
}

// ---------------------------------------------------------------------------
// Column softmax over channel axis (stride 1024 floats, length 1024).
// block (32 n-lanes, 8 c-parallel); grid (n-tiles=32, batch=32).
// ---------------------------------------------------------------------------
__global__ void col_softmax_kernel(float* __restrict__ data)
{
    const int b  = blockIdx.y;
    const int tx = threadIdx.x;                    // 0..31
    const int ty = threadIdx.y;                    // 0..7
    const int n  = blockIdx.x * 32 + tx;
    float* base = data + (long)b * ELEM_PER_B + n;

    __shared__ float red[8][32];

    float m = -1e30f;
    for (int c = ty; c < 1024; c += 8)
        m = fmaxf(m, base[(long)c << 10]);
    red[ty][tx] = m;
    __syncthreads();
    m = -1e30f;
#pragma unroll
    for (int j = 0; j < 8; j++) m = fmaxf(m, red[j][tx]);
    __syncthreads();

    float s = 0.0f;
    for (int c = ty; c < 1024; c += 8)
        s += __expf(base[(long)c << 10] - m);
    red[ty][tx] = s;
    __syncthreads();
    s = 0.0f;
#pragma unroll
    for (int j = 0; j < 8; j++) s += red[j][tx];
    float inv = 1.0f / s;

    for (int c = ty; c < 1024; c += 8) {
        long idx = (long)c << 10;
        base[idx] = __expf(base[idx] - m) * inv;
    }
}

// ---------------------------------------------------------------------------
// Launch
// ---------------------------------------------------------------------------
extern "C" void kernel_launch(void* const* d_in, const int* in_sizes, int n_in,
                              void* d_out, int out_size)
{
    (void)in_sizes; (void)n_in; (void)out_size;

    const float* x  = (const float*)d_in[0];   // [32, 2048, 32, 32]
    const float* wr = (const float*)d_in[1];   // [1024, 2048]
    const float* br = (const float*)d_in[2];   // [1024]
    const float* wc = (const float*)d_in[3];   // [1024, 1024]
    const float* bc = (const float*)d_in[4];   // [1024]
    const float* wd = (const float*)d_in[5];   // [1024, 1024]
    const float* bd = (const float*)d_in[6];   // [1024]
    float* out = (float*)d_out;                // [32, 1024, 32, 32]

    float *y1, *cbuf, *dbuf;
    cudaGetSymbolAddress((void**)&y1,   g_Y1);
    cudaGetSymbolAddress((void**)&cbuf, g_C);
    cudaGetSymbolAddress((void**)&dbuf, g_D);

    dim3 blk(256), g(8, 8, NB);

    // Y1 = Wr @ X_b + br     (K = 2048, B is [K,N] per batch)
    gemm_f32<false, true, false><<<g, blk>>>(
        wr, 0L, x, (long)2048 * 1024, br, nullptr, y1, MM, NN, 2048);

    // C = Wc @ Y1 + bc
    gemm_f32<false, true, false><<<g, blk>>>(
        wc, 0L, y1, (long)ELEM_PER_B, bc, nullptr, cbuf, MM, NN, 1024);

    // D = Wd @ Y1 + bd
    gemm_f32<false, true, false><<<g, blk>>>(
        wd, 0L, y1, (long)ELEM_PER_B, bd, nullptr, dbuf, MM, NN, 1024);

    // softmaxes
    row_softmax_kernel<<<NB * 1024, 256>>>(cbuf);
    col_softmax_kernel<<<dim3(32, NB), dim3(32, 8)>>>(dbuf);

    // out = Y1 + C @ D^T     (both per batch; TRANSB)
    gemm_f32<true, false, true><<<g, blk>>>(
        cbuf, (long)ELEM_PER_B, dbuf, (long)ELEM_PER_B,
        nullptr, y1, out, MM, NN, 1024);
}

// round 4
// speedup vs baseline: 1.0007x; 1.0007x over previous
#include <cuda_runtime.h>
#include <cuda_bf16.h>

// ---------------------------------------------------------------------------
// PSAttention (B=32, CIN=2048, COUT=HW=1024)
//   Y1 = Wr @ X_b + br                      [1024 x 1024] per batch, K=2048
//   C  = softmax_rows( Wc @ Y1 + bc )       softmax over hw (last axis)
//   D  = softmax_cols( Wd @ Y1 + bd )       softmax over channel axis
//   out = Y1 + C @ D^T                      per batch, K=1024
// All fp32.  GEMMs use packed fma.rn.f32x2 (Blackwell FFMA2, 2x fp32 rate).
// ---------------------------------------------------------------------------

#define NB   32
#define MM   1024
#define NN   1024
#define ELEM_PER_B (1024 * 1024)

// Scratch: 3 x 128 MB device globals (no cudaMalloc allowed).
__device__ float g_Y1[NB * ELEM_PER_B];
__device__ float g_C [NB * ELEM_PER_B];
__device__ float g_D [NB * ELEM_PER_B];

// ---- f32x2 helpers --------------------------------------------------------
__device__ __forceinline__ unsigned long long pack_dup(float a) {
    unsigned long long r;
    asm("mov.b64 %0, {%1, %1};" : "=l"(r) : "f"(a));
    return r;
}
__device__ __forceinline__ void fma2(unsigned long long& d,
                                     unsigned long long a,
                                     unsigned long long b) {
    asm("fma.rn.f32x2 %0, %1, %2, %0;" : "+l"(d) : "l"(a), "l"(b));
}
union U64F2 { unsigned long long u; float2 f; };

// ---------------------------------------------------------------------------
// Generic fp32 GEMM: C[M,N] = A[M,K] * B (+bias[m]) (+addend[m,n])
//   TRANSB=false : B is [K,N] row-major (element B[k*N + n])
//   TRANSB=true  : B is [N,K] row-major (element B[n*K + k])  -> C = A * B^T
// Tile 128x128x16, 256 threads, 8x8 per thread, f32x2 accumulators.
// ---------------------------------------------------------------------------
template<bool TRANSB, bool BIAS, bool ADDEND>
__global__ __launch_bounds__(256, 2)
void gemm_f32(const float* __restrict__ A, long strideA,
              const float* __restrict__ B, long strideB,
              const float* __restrict__ bias,
              const float* __restrict__ addend,
              float* __restrict__ C,
              int M, int N, int K)
{
    __shared__ float As[16][128];
    __shared__ float Bs[16][128];

    const int tid  = threadIdx.x;      // 0..255
    const int tx   = tid & 15;         // n-tile lane
    const int ty   = tid >> 4;         // m-tile lane
    const int bz   = blockIdx.z;
    const int row0 = blockIdx.y * 128;
    const int col0 = blockIdx.x * 128;

    const float* Ab = A + (long)bz * strideA;
    const float* Bb = B + (long)bz * strideB;
    float*       Cb = C + (long)bz * (long)M * N;

    // A / B(T) loader: 128 rows x 16 cols, float4 along K, 2 passes
    const int aRow = tid >> 2;         // 0..63
    const int aCol = (tid & 3) << 2;   // 0,4,8,12
    // B(N) loader: 16 rows x 128 cols, float4 along N, 2 passes
    const int bRow = tid >> 5;         // 0..7
    const int bCol = (tid & 31) << 2;  // 0..124

    unsigned long long acc[8][4];
#pragma unroll
    for (int i = 0; i < 8; i++)
#pragma unroll
        for (int j = 0; j < 4; j++) acc[i][j] = 0ULL;

    const int numT = K >> 4;
    float4 pa[2], pb[2];

    // prefetch of one K-tile into registers
    auto load_global = [&](int k0) {
        pa[0] = *(const float4*)&Ab[(long)(row0 + aRow     ) * K + k0 + aCol];
        pa[1] = *(const float4*)&Ab[(long)(row0 + aRow + 64) * K + k0 + aCol];
        if (TRANSB) {
            pb[0] = *(const float4*)&Bb[(long)(col0 + aRow     ) * K + k0 + aCol];
            pb[1] = *(const float4*)&Bb[(long)(col0 + aRow + 64) * K + k0 + aCol];
        } else {
            pb[0] = *(const float4*)&Bb[(long)(k0 + bRow    ) * N + col0 + bCol];
            pb[1] = *(const float4*)&Bb[(long)(k0 + bRow + 8) * N + col0 + bCol];
        }
    };
    auto store_smem = [&]() {
        As[aCol + 0][aRow] = pa[0].x;  As[aCol + 1][aRow] = pa[0].y;
        As[aCol + 2][aRow] = pa[0].z;  As[aCol + 3][aRow] = pa[0].w;
        As[aCol + 0][aRow + 64] = pa[1].x;  As[aCol + 1][aRow + 64] = pa[1].y;
        As[aCol + 2][aRow + 64] = pa[1].z;  As[aCol + 3][aRow + 64] = pa[1].w;
        if (TRANSB) {
            Bs[aCol + 0][aRow] = pb[0].x;  Bs[aCol + 1][aRow] = pb[0].y;
            Bs[aCol + 2][aRow] = pb[0].z;  Bs[aCol + 3][aRow] = pb[0].w;
            Bs[aCol + 0][aRow + 64] = pb[1].x;  Bs[aCol + 1][aRow + 64] = pb[1].y;
            Bs[aCol + 2][aRow + 64] = pb[1].z;  Bs[aCol + 3][aRow + 64] = pb[1].w;
        } else {
            *(float4*)&Bs[bRow    ][bCol] = pb[0];
            *(float4*)&Bs[bRow + 8][bCol] = pb[1];
        }
    };

    load_global(0);
    store_smem();
    __syncthreads();

    for (int t = 0; t < numT; t++) {
        if (t + 1 < numT) load_global((t + 1) << 4);

#pragma unroll
        for (int k = 0; k < 16; k++) {
            float4 a0 = *(const float4*)&As[k][ty * 8];
            float4 a1 = *(const float4*)&As[k][ty * 8 + 4];
            const unsigned long long* bsp =
                (const unsigned long long*)&Bs[k][tx * 8];
            unsigned long long bp0 = bsp[0], bp1 = bsp[1];
            unsigned long long bp2 = bsp[2], bp3 = bsp[3];
            float av[8] = {a0.x, a0.y, a0.z, a0.w, a1.x, a1.y, a1.z, a1.w};
#pragma unroll
            for (int i = 0; i < 8; i++) {
                unsigned long long ap = pack_dup(av[i]);
                fma2(acc[i][0], ap, bp0);
                fma2(acc[i][1], ap, bp1);
                fma2(acc[i][2], ap, bp2);
                fma2(acc[i][3], ap, bp3);
            }
        }
        __syncthreads();
        if (t + 1 < numT) store_smem();
        __syncthreads();
    }

    // epilogue
    const float* ad = ADDEND ? (addend + (long)bz * (long)M * N) : nullptr;
#pragma unroll
    for (int i = 0; i < 8; i++) {
        int  row  = row0 + ty * 8 + i;
        float bv  = BIAS ? __ldg(&bias[row]) : 0.0f;
        long base = (long)row * N + col0 + tx * 8;
#pragma unroll
        for (int j = 0; j < 4; j++) {
            U64F2 cv; cv.u = acc[i][j];
            float r0 = cv.f.x + bv;
            float r1 = cv.f.y + bv;
            if (ADDEND) {
                r0 += ad[base + 2 * j];
                r1 += ad[base + 2 * j + 1];
            }
            float2 o; o.x = r0; o.y = r1;
            *(float2*)&Cb[base + 2 * j] = o;
        }
    }
}

// ---------------------------------------------------------------------------
// Row softmax over last axis (length 1024). One block per (b, c) row.
// ---------------------------------------------------------------------------
__global__ void row_softmax_kernel(float* __restrict__ data)
{
    long row = blockIdx.x;
    float4* p = reinterpret_cast<float4*>(data + row * 1024);
    int t = threadIdx.x;               // 256 threads, 4 floats each

    float4 v = p[t];
    float m = fmaxf(fmaxf(v.x, v.y), fmaxf(v.z, v.w));

    __shared__ float red[256];
    red[t] = m;
    __syncthreads();
    for (int s = 128; s > 0; s >>= 1) {
        if (t < s) red[t] = fmaxf(red[t], red[t + s]);
        __syncthreads();
    }
    m = red[0];
    __syncthreads();

    float4 e;
    e.x = __expf(v.x - m); e.y = __expf(v.y - m);
    e.z = __expf(v.z - m); e.w = __expf(v.w - m);
    float s4 = e.x + e.y + e.z + e.w;

    red[t] = s4;
    __syncthreads();
    for (int s = 128; s > 0; s >>= 1) {
        if (t < s) red[t] += red[t + s];
        __syncthreads();
    }
    float inv = 1.0f / red[0];

    e.x *= inv; e.y *= inv; e.z *= inv; e.w *= inv;
    p[t] = e;
}

// ---------------------------------------------------------------------------
// Column softmax over channel axis (stride 1024 floats, length 1024).
// block (32 n-lanes, 8 c-parallel); grid (n-tiles=32, batch=32).
// ---------------------------------------------------------------------------
__global__ void col_softmax_kernel(float* __restrict__ data)
{
    const int b  = blockIdx.y;
    const int tx = threadIdx.x;                    // 0..31
    const int ty = threadIdx.y;                    // 0..7
    const int n  = blockIdx.x * 32 + tx;
    float* base = data + (long)b * ELEM_PER_B + n;

    __shared__ float red[8][32];

    float m = -1e30f;
    for (int c = ty; c < 1024; c += 8)
        m = fmaxf(m, base[(long)c << 10]);
    red[ty][tx] = m;
    __syncthreads();
    m = -1e30f;
#pragma unroll
    for (int j = 0; j < 8; j++) m = fmaxf(m, red[j][tx]);
    __syncthreads();

    float s = 0.0f;
    for (int c = ty; c < 1024; c += 8)
        s += __expf(base[(long)c << 10] - m);
    red[ty][tx] = s;
    __syncthreads();
    s = 0.0f;
#pragma unroll
    for (int j = 0; j < 8; j++) s += red[j][tx];
    float inv = 1.0f / s;

    for (int c = ty; c < 1024; c += 8) {
        long idx = (long)c << 10;
        base[idx] = __expf(base[idx] - m) * inv;
    }
}

// ---------------------------------------------------------------------------
// Launch
// ---------------------------------------------------------------------------
extern "C" void kernel_launch(void* const* d_in, const int* in_sizes, int n_in,
                              void* d_out, int out_size)
{
    (void)in_sizes; (void)n_in; (void)out_size;

    const float* x  = (const float*)d_in[0];   // [32, 2048, 32, 32]
    const float* wr = (const float*)d_in[1];   // [1024, 2048]
    const float* br = (const float*)d_in[2];   // [1024]
    const float* wc = (const float*)d_in[3];   // [1024, 1024]
    const float* bc = (const float*)d_in[4];   // [1024]
    const float* wd = (const float*)d_in[5];   // [1024, 1024]
    const float* bd = (const float*)d_in[6];   // [1024]
    float* out = (float*)d_out;                // [32, 1024, 32, 32]

    float *y1, *cbuf, *dbuf;
    cudaGetSymbolAddress((void**)&y1,   g_Y1);
    cudaGetSymbolAddress((void**)&cbuf, g_C);
    cudaGetSymbolAddress((void**)&dbuf, g_D);

    dim3 blk(256), g(8, 8, NB);

    // Y1 = Wr @ X_b + br     (K = 2048, B is [K,N] per batch)
    gemm_f32<false, true, false><<<g, blk>>>(
        wr, 0L, x, (long)2048 * 1024, br, nullptr, y1, MM, NN, 2048);

    // C = Wc @ Y1 + bc
    gemm_f32<false, true, false><<<g, blk>>>(
        wc, 0L, y1, (long)ELEM_PER_B, bc, nullptr, cbuf, MM, NN, 1024);

    // D = Wd @ Y1 + bd
    gemm_f32<false, true, false><<<g, blk>>>(
        wd, 0L, y1, (long)ELEM_PER_B, bd, nullptr, dbuf, MM, NN, 1024);

    // softmaxes
    row_softmax_kernel<<<NB * 1024, 256>>>(cbuf);
    col_softmax_kernel<<<dim3(32, NB), dim3(32, 8)>>>(dbuf);

    // out = Y1 + C @ D^T     (both per batch; TRANSB)
    gemm_f32<true, false, true><<<g, blk>>>(
        cbuf, (long)ELEM_PER_B, dbuf, (long)ELEM_PER_B,
        nullptr, y1, out, MM, NN, 1024);
}

// round 5
// speedup vs baseline: 1.0012x; 1.0005x over previous
#include <cuda_runtime.h>
#include <cuda_bf16.h>

// ---------------------------------------------------------------------------
// PSAttention (B=32, CIN=2048, COUT=HW=1024)
//   Y1 = Wr @ X_b + br                      [1024 x 1024] per batch, K=2048
//   C  = softmax_rows( Wc @ Y1 + bc )       softmax over hw (last axis)
//   D  = softmax_cols( Wd @ Y1 + bd )       softmax over channel axis
//   out = Y1 + C @ D^T                      per batch, K=1024
// All fp32.  GEMMs use packed fma.rn.f32x2 (Blackwell FFMA2, 2x fp32 rate).
// ---------------------------------------------------------------------------

#define NB   32
#define MM   1024
#define NN   1024
#define ELEM_PER_B (1024 * 1024)

// Scratch: 3 x 128 MB device globals (no cudaMalloc allowed).
__device__ float g_Y1[NB * ELEM_PER_B];
__device__ float g_C [NB * ELEM_PER_B];
__device__ float g_D [NB * ELEM_PER_B];

// ---- f32x2 helpers --------------------------------------------------------
__device__ __forceinline__ unsigned long long pack_dup(float a) {
    unsigned long long r;
    asm("mov.b64 %0, {%1, %1};" : "=l"(r) : "f"(a));
    return r;
}
__device__ __forceinline__ void fma2(unsigned long long& d,
                                     unsigned long long a,
                                     unsigned long long b) {
    asm("fma.rn.f32x2 %0, %1, %2, %0;" : "+l"(d) : "l"(a), "l"(b));
}
union U64F2 { unsigned long long u; float2 f; };

// ---------------------------------------------------------------------------
// Generic fp32 GEMM: C[M,N] = A[M,K] * B (+bias[m]) (+addend[m,n])
//   TRANSB=false : B is [K,N] row-major (element B[k*N + n])
//   TRANSB=true  : B is [N,K] row-major (element B[n*K + k])  -> C = A * B^T
// Tile 128x128x16, 256 threads, 8x8 per thread, f32x2 accumulators.
// ---------------------------------------------------------------------------
template<bool TRANSB, bool BIAS, bool ADDEND>
__global__ __launch_bounds__(256, 2)
void gemm_f32(const float* __restrict__ A, long strideA,
              const float* __restrict__ B, long strideB,
              const float* __restrict__ bias,
              const float* __restrict__ addend,
              float* __restrict__ C,
              int M, int N, int K)
{
    __shared__ float As[16][128];
    __shared__ float Bs[16][128];

    const int tid  = threadIdx.x;      // 0..255
    const int tx   = tid & 15;         // n-tile lane
    const int ty   = tid >> 4;         // m-tile lane
    const int bz   = blockIdx.z;
    const int row0 = blockIdx.y * 128;
    const int col0 = blockIdx.x * 128;

    const float* Ab = A + (long)bz * strideA;
    const float* Bb = B + (long)bz * strideB;
    float*       Cb = C + (long)bz * (long)M * N;

    // A / B(T) loader: 128 rows x 16 cols, float4 along K, 2 passes
    const int aRow = tid >> 2;         // 0..63
    const int aCol = (tid & 3) << 2;   // 0,4,8,12
    // B(N) loader: 16 rows x 128 cols, float4 along N, 2 passes
    const int bRow = tid >> 5;         // 0..7
    const int bCol = (tid & 31) << 2;  // 0..124

    unsigned long long acc[8][4];
#pragma unroll
    for (int i = 0; i < 8; i++)
#pragma unroll
        for (int j = 0; j < 4; j++) acc[i][j] = 0ULL;

    const int numT = K >> 4;
    float4 pa[2], pb[2];

    // prefetch of one K-tile into registers
    auto load_global = [&](int k0) {
        pa[0] = *(const float4*)&Ab[(long)(row0 + aRow     ) * K + k0 + aCol];
        pa[1] = *(const float4*)&Ab[(long)(row0 + aRow + 64) * K + k0 + aCol];
        if (TRANSB) {
            pb[0] = *(const float4*)&Bb[(long)(col0 + aRow     ) * K + k0 + aCol];
            pb[1] = *(const float4*)&Bb[(long)(col0 + aRow + 64) * K + k0 + aCol];
        } else {
            pb[0] = *(const float4*)&Bb[(long)(k0 + bRow    ) * N + col0 + bCol];
            pb[1] = *(const float4*)&Bb[(long)(k0 + bRow + 8) * N + col0 + bCol];
        }
    };
    auto store_smem = [&]() {
        As[aCol + 0][aRow] = pa[0].x;  As[aCol + 1][aRow] = pa[0].y;
        As[aCol + 2][aRow] = pa[0].z;  As[aCol + 3][aRow] = pa[0].w;
        As[aCol + 0][aRow + 64] = pa[1].x;  As[aCol + 1][aRow + 64] = pa[1].y;
        As[aCol + 2][aRow + 64] = pa[1].z;  As[aCol + 3][aRow + 64] = pa[1].w;
        if (TRANSB) {
            Bs[aCol + 0][aRow] = pb[0].x;  Bs[aCol + 1][aRow] = pb[0].y;
            Bs[aCol + 2][aRow] = pb[0].z;  Bs[aCol + 3][aRow] = pb[0].w;
            Bs[aCol + 0][aRow + 64] = pb[1].x;  Bs[aCol + 1][aRow + 64] = pb[1].y;
            Bs[aCol + 2][aRow + 64] = pb[1].z;  Bs[aCol + 3][aRow + 64] = pb[1].w;
        } else {
            *(float4*)&Bs[bRow    ][bCol] = pb[0];
            *(float4*)&Bs[bRow + 8][bCol] = pb[1];
        }
    };

    load_global(0);
    store_smem();
    __syncthreads();

    for (int t = 0; t < numT; t++) {
        if (t + 1 < numT) load_global((t + 1) << 4);

#pragma unroll
        for (int k = 0; k < 16; k++) {
            float4 a0 = *(const float4*)&As[k][ty * 8];
            float4 a1 = *(const float4*)&As[k][ty * 8 + 4];
            const unsigned long long* bsp =
                (const unsigned long long*)&Bs[k][tx * 8];
            unsigned long long bp0 = bsp[0], bp1 = bsp[1];
            unsigned long long bp2 = bsp[2], bp3 = bsp[3];
            float av[8] = {a0.x, a0.y, a0.z, a0.w, a1.x, a1.y, a1.z, a1.w};
#pragma unroll
            for (int i = 0; i < 8; i++) {
                unsigned long long ap = pack_dup(av[i]);
                fma2(acc[i][0], ap, bp0);
                fma2(acc[i][1], ap, bp1);
                fma2(acc[i][2], ap, bp2);
                fma2(acc[i][3], ap, bp3);
            }
        }
        __syncthreads();
        if (t + 1 < numT) store_smem();
        __syncthreads();
    }

    // epilogue
    const float* ad = ADDEND ? (addend + (long)bz * (long)M * N) : nullptr;
#pragma unroll
    for (int i = 0; i < 8; i++) {
        int  row  = row0 + ty * 8 + i;
        float bv  = BIAS ? __ldg(&bias[row]) : 0.0f;
        long base = (long)row * N + col0 + tx * 8;
#pragma unroll
        for (int j = 0; j < 4; j++) {
            U64F2 cv; cv.u = acc[i][j];
            float r0 = cv.f.x + bv;
            float r1 = cv.f.y + bv;
            if (ADDEND) {
                r0 += ad[base + 2 * j];
                r1 += ad[base + 2 * j + 1];
            }
            float2 o; o.x = r0; o.y = r1;
            *(float2*)&Cb[base + 2 * j] = o;
        }
    }
}

// ---------------------------------------------------------------------------
// Row softmax over last axis (length 1024). One block per (b, c) row.
// ---------------------------------------------------------------------------
__global__ void row_softmax_kernel(float* __restrict__ data)
{
    long row = blockIdx.x;
    float4* p = reinterpret_cast<float4*>(data + row * 1024);
    int t = threadIdx.x;               // 256 threads, 4 floats each

    float4 v = p[t];
    float m = fmaxf(fmaxf(v.x, v.y), fmaxf(v.z, v.w));

    __shared__ float red[256];
    red[t] = m;
    __syncthreads();
    for (int s = 128; s > 0; s >>= 1) {
        if (t < s) red[t] = fmaxf(red[t], red[t + s]);
        __syncthreads();
    }
    m = red[0];
    __syncthreads();

    float4 e;
    e.x = __expf(v.x - m); e.y = __expf(v.y - m);
    e.z = __expf(v.z - m); e.w = __expf(v.w - m);
    float s4 = e.x + e.y + e.z + e.w;

    red[t] = s4;
    __syncthreads();
    for (int s = 128; s > 0; s >>= 1) {
        if (t < s) red[t] += red[t + s];
        __syncthreads();
    }
    float inv = 1.0f / red[0];

    e.x *= inv; e.y *= inv; e.z *= inv; e.w *= inv;
    p[t] = e;
}

// ---------------------------------------------------------------------------
// Column softmax over channel axis (stride 1024 floats, length 1024).
// block (32 n-lanes, 8 c-parallel); grid (n-tiles=32, batch=32).
// ---------------------------------------------------------------------------
__global__ void col_softmax_kernel(float* __restrict__ data)
{
    const int b  = blockIdx.y;
    const int tx = threadIdx.x;                    // 0..31
    const int ty = threadIdx.y;                    // 0..7
    const int n  = blockIdx.x * 32 + tx;
    float* base = data + (long)b * ELEM_PER_B + n;

    __shared__ float red[8][32];

    float m = -1e30f;
    for (int c = ty; c < 1024; c += 8)
        m = fmaxf(m, base[(long)c << 10]);
    red[ty][tx] = m;
    __syncthreads();
    m = -1e30f;
#pragma unroll
    for (int j = 0; j < 8; j++) m = fmaxf(m, red[j][tx]);
    __syncthreads();

    float s = 0.0f;
    for (int c = ty; c < 1024; c += 8)
        s += __expf(base[(long)c << 10] - m);
    red[ty][tx] = s;
    __syncthreads();
    s = 0.0f;
#pragma unroll
    for (int j = 0; j < 8; j++) s += red[j][tx];
    float inv = 1.0f / s;

    for (int c = ty; c < 1024; c += 8) {
        long idx = (long)c << 10;
        base[idx] = __expf(base[idx] - m) * inv;
    }
}

// ---------------------------------------------------------------------------
// Launch
// ---------------------------------------------------------------------------
extern "C" void kernel_launch(void* const* d_in, const int* in_sizes, int n_in,
                              void* d_out, int out_size)
{
    (void)in_sizes; (void)n_in; (void)out_size;

    const float* x  = (const float*)d_in[0];   // [32, 2048, 32, 32]
    const float* wr = (const float*)d_in[1];   // [1024, 2048]
    const float* br = (const float*)d_in[2];   // [1024]
    const float* wc = (const float*)d_in[3];   // [1024, 1024]
    const float* bc = (const float*)d_in[4];   // [1024]
    const float* wd = (const float*)d_in[5];   // [1024, 1024]
    const float* bd = (const float*)d_in[6];   // [1024]
    float* out = (float*)d_out;                // [32, 1024, 32, 32]

    float *y1, *cbuf, *dbuf;
    cudaGetSymbolAddress((void**)&y1,   g_Y1);
    cudaGetSymbolAddress((void**)&cbuf, g_C);
    cudaGetSymbolAddress((void**)&dbuf, g_D);

    dim3 blk(256), g(8, 8, NB);

    // Y1 = Wr @ X_b + br     (K = 2048, B is [K,N] per batch)
    gemm_f32<false, true, false><<<g, blk>>>(
        wr, 0L, x, (long)2048 * 1024, br, nullptr, y1, MM, NN, 2048);

    // C = Wc @ Y1 + bc
    gemm_f32<false, true, false><<<g, blk>>>(
        wc, 0L, y1, (long)ELEM_PER_B, bc, nullptr, cbuf, MM, NN, 1024);

    // D = Wd @ Y1 + bd
    gemm_f32<false, true, false><<<g, blk>>>(
        wd, 0L, y1, (long)ELEM_PER_B, bd, nullptr, dbuf, MM, NN, 1024);

    // softmaxes
    row_softmax_kernel<<<NB * 1024, 256>>>(cbuf);
    col_softmax_kernel<<<dim3(32, NB), dim3(32, 8)>>>(dbuf);

    // out = Y1 + C @ D^T     (both per batch; TRANSB)
    gemm_f32<true, false, true><<<g, blk>>>(
        cbuf, (long)ELEM_PER_B, dbuf, (long)ELEM_PER_B,
        nullptr, y1, out, MM, NN, 1024);
}

// round 6
// speedup vs baseline: 1.0020x; 1.0008x over previous
#include <cuda_runtime.h>
#include <cuda_bf16.h>

// ---------------------------------------------------------------------------
// PSAttention (B=32, CIN=2048, COUT=HW=1024)
//   Y1 = Wr @ X_b + br                      [1024 x 1024] per batch, K=2048
//   C  = softmax_rows( Wc @ Y1 + bc )       softmax over hw (last axis)
//   D  = softmax_cols( Wd @ Y1 + bd )       softmax over channel axis
//   out = Y1 + C @ D^T                      per batch, K=1024
// All fp32.  GEMMs use packed fma.rn.f32x2 (Blackwell FFMA2, 2x fp32 rate).
// ---------------------------------------------------------------------------

#define NB   32
#define MM   1024
#define NN   1024
#define ELEM_PER_B (1024 * 1024)

// Scratch: 3 x 128 MB device globals (no cudaMalloc allowed).
__device__ float g_Y1[NB * ELEM_PER_B];
__device__ float g_C [NB * ELEM_PER_B];
__device__ float g_D [NB * ELEM_PER_B];

// ---- f32x2 helpers --------------------------------------------------------
__device__ __forceinline__ unsigned long long pack_dup(float a) {
    unsigned long long r;
    asm("mov.b64 %0, {%1, %1};" : "=l"(r) : "f"(a));
    return r;
}
__device__ __forceinline__ void fma2(unsigned long long& d,
                                     unsigned long long a,
                                     unsigned long long b) {
    asm("fma.rn.f32x2 %0, %1, %2, %0;" : "+l"(d) : "l"(a), "l"(b));
}
union U64F2 { unsigned long long u; float2 f; };

// ---------------------------------------------------------------------------
// Generic fp32 GEMM: C[M,N] = A[M,K] * B (+bias[m]) (+addend[m,n])
//   TRANSB=false : B is [K,N] row-major (element B[k*N + n])
//   TRANSB=true  : B is [N,K] row-major (element B[n*K + k])  -> C = A * B^T
// Tile 128x128x16, 256 threads, 8x8 per thread, f32x2 accumulators.
// ---------------------------------------------------------------------------
template<bool TRANSB, bool BIAS, bool ADDEND>
__global__ __launch_bounds__(256, 2)
void gemm_f32(const float* __restrict__ A, long strideA,
              const float* __restrict__ B, long strideB,
              const float* __restrict__ bias,
              const float* __restrict__ addend,
              float* __restrict__ C,
              int M, int N, int K)
{
    __shared__ float As[16][128];
    __shared__ float Bs[16][128];

    const int tid  = threadIdx.x;      // 0..255
    const int tx   = tid & 15;         // n-tile lane
    const int ty   = tid >> 4;         // m-tile lane
    const int bz   = blockIdx.z;
    const int row0 = blockIdx.y * 128;
    const int col0 = blockIdx.x * 128;

    const float* Ab = A + (long)bz * strideA;
    const float* Bb = B + (long)bz * strideB;
    float*       Cb = C + (long)bz * (long)M * N;

    // A / B(T) loader: 128 rows x 16 cols, float4 along K, 2 passes
    const int aRow = tid >> 2;         // 0..63
    const int aCol = (tid & 3) << 2;   // 0,4,8,12
    // B(N) loader: 16 rows x 128 cols, float4 along N, 2 passes
    const int bRow = tid >> 5;         // 0..7
    const int bCol = (tid & 31) << 2;  // 0..124

    unsigned long long acc[8][4];
#pragma unroll
    for (int i = 0; i < 8; i++)
#pragma unroll
        for (int j = 0; j < 4; j++) acc[i][j] = 0ULL;

    const int numT = K >> 4;
    float4 pa[2], pb[2];

    // prefetch of one K-tile into registers
    auto load_global = [&](int k0) {
        pa[0] = *(const float4*)&Ab[(long)(row0 + aRow     ) * K + k0 + aCol];
        pa[1] = *(const float4*)&Ab[(long)(row0 + aRow + 64) * K + k0 + aCol];
        if (TRANSB) {
            pb[0] = *(const float4*)&Bb[(long)(col0 + aRow     ) * K + k0 + aCol];
            pb[1] = *(const float4*)&Bb[(long)(col0 + aRow + 64) * K + k0 + aCol];
        } else {
            pb[0] = *(const float4*)&Bb[(long)(k0 + bRow    ) * N + col0 + bCol];
            pb[1] = *(const float4*)&Bb[(long)(k0 + bRow + 8) * N + col0 + bCol];
        }
    };
    auto store_smem = [&]() {
        As[aCol + 0][aRow] = pa[0].x;  As[aCol + 1][aRow] = pa[0].y;
        As[aCol + 2][aRow] = pa[0].z;  As[aCol + 3][aRow] = pa[0].w;
        As[aCol + 0][aRow + 64] = pa[1].x;  As[aCol + 1][aRow + 64] = pa[1].y;
        As[aCol + 2][aRow + 64] = pa[1].z;  As[aCol + 3][aRow + 64] = pa[1].w;
        if (TRANSB) {
            Bs[aCol + 0][aRow] = pb[0].x;  Bs[aCol + 1][aRow] = pb[0].y;
            Bs[aCol + 2][aRow] = pb[0].z;  Bs[aCol + 3][aRow] = pb[0].w;
            Bs[aCol + 0][aRow + 64] = pb[1].x;  Bs[aCol + 1][aRow + 64] = pb[1].y;
            Bs[aCol + 2][aRow + 64] = pb[1].z;  Bs[aCol + 3][aRow + 64] = pb[1].w;
        } else {
            *(float4*)&Bs[bRow    ][bCol] = pb[0];
            *(float4*)&Bs[bRow + 8][bCol] = pb[1];
        }
    };

    load_global(0);
    store_smem();
    __syncthreads();

    for (int t = 0; t < numT; t++) {
        if (t + 1 < numT) load_global((t + 1) << 4);

#pragma unroll
        for (int k = 0; k < 16; k++) {
            float4 a0 = *(const float4*)&As[k][ty * 8];
            float4 a1 = *(const float4*)&As[k][ty * 8 + 4];
            const unsigned long long* bsp =
                (const unsigned long long*)&Bs[k][tx * 8];
            unsigned long long bp0 = bsp[0], bp1 = bsp[1];
            unsigned long long bp2 = bsp[2], bp3 = bsp[3];
            float av[8] = {a0.x, a0.y, a0.z, a0.w, a1.x, a1.y, a1.z, a1.w};
#pragma unroll
            for (int i = 0; i < 8; i++) {
                unsigned long long ap = pack_dup(av[i]);
                fma2(acc[i][0], ap, bp0);
                fma2(acc[i][1], ap, bp1);
                fma2(acc[i][2], ap, bp2);
                fma2(acc[i][3], ap, bp3);
            }
        }
        __syncthreads();
        if (t + 1 < numT) store_smem();
        __syncthreads();
    }

    // epilogue
    const float* ad = ADDEND ? (addend + (long)bz * (long)M * N) : nullptr;
#pragma unroll
    for (int i = 0; i < 8; i++) {
        int  row  = row0 + ty * 8 + i;
        float bv  = BIAS ? __ldg(&bias[row]) : 0.0f;
        long base = (long)row * N + col0 + tx * 8;
#pragma unroll
        for (int j = 0; j < 4; j++) {
            U64F2 cv; cv.u = acc[i][j];
            float r0 = cv.f.x + bv;
            float r1 = cv.f.y + bv;
            if (ADDEND) {
                r0 += ad[base + 2 * j];
                r1 += ad[base + 2 * j + 1];
            }
            float2 o; o.x = r0; o.y = r1;
            *(float2*)&Cb[base + 2 * j] = o;
        }
    }
}

// ---------------------------------------------------------------------------
// Row softmax over last axis (length 1024). One block per (b, c) row.
// ---------------------------------------------------------------------------
__global__ void row_softmax_kernel(float* __restrict__ data)
{
    long row = blockIdx.x;
    float4* p = reinterpret_cast<float4*>(data + row * 1024);
    int t = threadIdx.x;               // 256 threads, 4 floats each

    float4 v = p[t];
    float m = fmaxf(fmaxf(v.x, v.y), fmaxf(v.z, v.w));

    __shared__ float red[256];
    red[t] = m;
    __syncthreads();
    for (int s = 128; s > 0; s >>= 1) {
        if (t < s) red[t] = fmaxf(red[t], red[t + s]);
        __syncthreads();
    }
    m = red[0];
    __syncthreads();

    float4 e;
    e.x = __expf(v.x - m); e.y = __expf(v.y - m);
    e.z = __expf(v.z - m); e.w = __expf(v.w - m);
    float s4 = e.x + e.y + e.z + e.w;

    red[t] = s4;
    __syncthreads();
    for (int s = 128; s > 0; s >>= 1) {
        if (t < s) red[t] += red[t + s];
        __syncthreads();
    }
    float inv = 1.0f / red[0];

    e.x *= inv; e.y *= inv; e.z *= inv; e.w *= inv;
    p[t] = e;
}

// ---------------------------------------------------------------------------
// Column softmax over channel axis (stride 1024 floats, length 1024).
// block (32 n-lanes, 8 c-parallel); grid (n-tiles=32, batch=32).
// ---------------------------------------------------------------------------
__global__ void col_softmax_kernel(float* __restrict__ data)
{
    const int b  = blockIdx.y;
    const int tx = threadIdx.x;                    // 0..31
    const int ty = threadIdx.y;                    // 0..7
    const int n  = blockIdx.x * 32 + tx;
    float* base = data + (long)b * ELEM_PER_B + n;

    __shared__ float red[8][32];

    float m = -1e30f;
    for (int c = ty; c < 1024; c += 8)
        m = fmaxf(m, base[(long)c << 10]);
    red[ty][tx] = m;
    __syncthreads();
    m = -1e30f;
#pragma unroll
    for (int j = 0; j < 8; j++) m = fmaxf(m, red[j][tx]);
    __syncthreads();

    float s = 0.0f;
    for (int c = ty; c < 1024; c += 8)
        s += __expf(base[(long)c << 10] - m);
    red[ty][tx] = s;
    __syncthreads();
    s = 0.0f;
#pragma unroll
    for (int j = 0; j < 8; j++) s += red[j][tx];
    float inv = 1.0f / s;

    for (int c = ty; c < 1024; c += 8) {
        long idx = (long)c << 10;
        base[idx] = __expf(base[idx] - m) * inv;
    }
}

// ---------------------------------------------------------------------------
// Launch
// ---------------------------------------------------------------------------
extern "C" void kernel_launch(void* const* d_in, const int* in_sizes, int n_in,
                              void* d_out, int out_size)
{
    (void)in_sizes; (void)n_in; (void)out_size;

    const float* x  = (const float*)d_in[0];   // [32, 2048, 32, 32]
    const float* wr = (const float*)d_in[1];   // [1024, 2048]
    const float* br = (const float*)d_in[2];   // [1024]
    const float* wc = (const float*)d_in[3];   // [1024, 1024]
    const float* bc = (const float*)d_in[4];   // [1024]
    const float* wd = (const float*)d_in[5];   // [1024, 1024]
    const float* bd = (const float*)d_in[6];   // [1024]
    float* out = (float*)d_out;                // [32, 1024, 32, 32]

    float *y1, *cbuf, *dbuf;
    cudaGetSymbolAddress((void**)&y1,   g_Y1);
    cudaGetSymbolAddress((void**)&cbuf, g_C);
    cudaGetSymbolAddress((void**)&dbuf, g_D);

    dim3 blk(256), g(8, 8, NB);

    // Y1 = Wr @ X_b + br     (K = 2048, B is [K,N] per batch)
    gemm_f32<false, true, false><<<g, blk>>>(
        wr, 0L, x, (long)2048 * 1024, br, nullptr, y1, MM, NN, 2048);

    // C = Wc @ Y1 + bc
    gemm_f32<false, true, false><<<g, blk>>>(
        wc, 0L, y1, (long)ELEM_PER_B, bc, nullptr, cbuf, MM, NN, 1024);

    // D = Wd @ Y1 + bd
    gemm_f32<false, true, false><<<g, blk>>>(
        wd, 0L, y1, (long)ELEM_PER_B, bd, nullptr, dbuf, MM, NN, 1024);

    // softmaxes
    row_softmax_kernel<<<NB * 1024, 256>>>(cbuf);
    col_softmax_kernel<<<dim3(32, NB), dim3(32, 8)>>>(dbuf);

    // out = Y1 + C @ D^T     (both per batch; TRANSB)
    gemm_f32<true, false, true><<<g, blk>>>(
        cbuf, (long)ELEM_PER_B, dbuf, (long)ELEM_PER_B,
        nullptr, y1, out, MM, NN, 1024);
}

// round 7
// speedup vs baseline: 1.0021x; 1.0000x over previous
#include <cuda_runtime.h>
#include <cuda_bf16.h>

// ---------------------------------------------------------------------------
// PSAttention (B=32, CIN=2048, COUT=HW=1024)
//   Y1 = Wr @ X_b + br                      [1024 x 1024] per batch, K=2048
//   C  = softmax_rows( Wc @ Y1 + bc )       softmax over hw (last axis)
//   D  = softmax_cols( Wd @ Y1 + bd )       softmax over channel axis
//   out = Y1 + C @ D^T                      per batch, K=1024
// All fp32.  GEMMs use packed fma.rn.f32x2 (Blackwell FFMA2, 2x fp32 rate).
// ---------------------------------------------------------------------------

#define NB   32
#define MM   1024
#define NN   1024
#define ELEM_PER_B (1024 * 1024)

// Scratch: 3 x 128 MB device globals (no cudaMalloc allowed).
__device__ float g_Y1[NB * ELEM_PER_B];
__device__ float g_C [NB * ELEM_PER_B];
__device__ float g_D [NB * ELEM_PER_B];

// ---- f32x2 helpers --------------------------------------------------------
__device__ __forceinline__ unsigned long long pack_dup(float a) {
    unsigned long long r;
    asm("mov.b64 %0, {%1, %1};" : "=l"(r) : "f"(a));
    return r;
}
__device__ __forceinline__ void fma2(unsigned long long& d,
                                     unsigned long long a,
                                     unsigned long long b) {
    asm("fma.rn.f32x2 %0, %1, %2, %0;" : "+l"(d) : "l"(a), "l"(b));
}
union U64F2 { unsigned long long u; float2 f; };

// ---------------------------------------------------------------------------
// Generic fp32 GEMM: C[M,N] = A[M,K] * B (+bias[m]) (+addend[m,n])
//   TRANSB=false : B is [K,N] row-major (element B[k*N + n])
//   TRANSB=true  : B is [N,K] row-major (element B[n*K + k])  -> C = A * B^T
// Tile 128x128x16, 256 threads, 8x8 per thread, f32x2 accumulators.
// ---------------------------------------------------------------------------
template<bool TRANSB, bool BIAS, bool ADDEND>
__global__ __launch_bounds__(256, 2)
void gemm_f32(const float* __restrict__ A, long strideA,
              const float* __restrict__ B, long strideB,
              const float* __restrict__ bias,
              const float* __restrict__ addend,
              float* __restrict__ C,
              int M, int N, int K)
{
    __shared__ float As[16][128];
    __shared__ float Bs[16][128];

    const int tid  = threadIdx.x;      // 0..255
    const int tx   = tid & 15;         // n-tile lane
    const int ty   = tid >> 4;         // m-tile lane
    const int bz   = blockIdx.z;
    const int row0 = blockIdx.y * 128;
    const int col0 = blockIdx.x * 128;

    const float* Ab = A + (long)bz * strideA;
    const float* Bb = B + (long)bz * strideB;
    float*       Cb = C + (long)bz * (long)M * N;

    // A / B(T) loader: 128 rows x 16 cols, float4 along K, 2 passes
    const int aRow = tid >> 2;         // 0..63
    const int aCol = (tid & 3) << 2;   // 0,4,8,12
    // B(N) loader: 16 rows x 128 cols, float4 along N, 2 passes
    const int bRow = tid >> 5;         // 0..7
    const int bCol = (tid & 31) << 2;  // 0..124

    unsigned long long acc[8][4];
#pragma unroll
    for (int i = 0; i < 8; i++)
#pragma unroll
        for (int j = 0; j < 4; j++) acc[i][j] = 0ULL;

    const int numT = K >> 4;
    float4 pa[2], pb[2];

    // prefetch of one K-tile into registers
    auto load_global = [&](int k0) {
        pa[0] = *(const float4*)&Ab[(long)(row0 + aRow     ) * K + k0 + aCol];
        pa[1] = *(const float4*)&Ab[(long)(row0 + aRow + 64) * K + k0 + aCol];
        if (TRANSB) {
            pb[0] = *(const float4*)&Bb[(long)(col0 + aRow     ) * K + k0 + aCol];
            pb[1] = *(const float4*)&Bb[(long)(col0 + aRow + 64) * K + k0 + aCol];
        } else {
            pb[0] = *(const float4*)&Bb[(long)(k0 + bRow    ) * N + col0 + bCol];
            pb[1] = *(const float4*)&Bb[(long)(k0 + bRow + 8) * N + col0 + bCol];
        }
    };
    auto store_smem = [&]() {
        As[aCol + 0][aRow] = pa[0].x;  As[aCol + 1][aRow] = pa[0].y;
        As[aCol + 2][aRow] = pa[0].z;  As[aCol + 3][aRow] = pa[0].w;
        As[aCol + 0][aRow + 64] = pa[1].x;  As[aCol + 1][aRow + 64] = pa[1].y;
        As[aCol + 2][aRow + 64] = pa[1].z;  As[aCol + 3][aRow + 64] = pa[1].w;
        if (TRANSB) {
            Bs[aCol + 0][aRow] = pb[0].x;  Bs[aCol + 1][aRow] = pb[0].y;
            Bs[aCol + 2][aRow] = pb[0].z;  Bs[aCol + 3][aRow] = pb[0].w;
            Bs[aCol + 0][aRow + 64] = pb[1].x;  Bs[aCol + 1][aRow + 64] = pb[1].y;
            Bs[aCol + 2][aRow + 64] = pb[1].z;  Bs[aCol + 3][aRow + 64] = pb[1].w;
        } else {
            *(float4*)&Bs[bRow    ][bCol] = pb[0];
            *(float4*)&Bs[bRow + 8][bCol] = pb[1];
        }
    };

    load_global(0);
    store_smem();
    __syncthreads();

    for (int t = 0; t < numT; t++) {
        if (t + 1 < numT) load_global((t + 1) << 4);

#pragma unroll
        for (int k = 0; k < 16; k++) {
            float4 a0 = *(const float4*)&As[k][ty * 8];
            float4 a1 = *(const float4*)&As[k][ty * 8 + 4];
            const unsigned long long* bsp =
                (const unsigned long long*)&Bs[k][tx * 8];
            unsigned long long bp0 = bsp[0], bp1 = bsp[1];
            unsigned long long bp2 = bsp[2], bp3 = bsp[3];
            float av[8] = {a0.x, a0.y, a0.z, a0.w, a1.x, a1.y, a1.z, a1.w};
#pragma unroll
            for (int i = 0; i < 8; i++) {
                unsigned long long ap = pack_dup(av[i]);
                fma2(acc[i][0], ap, bp0);
                fma2(acc[i][1], ap, bp1);
                fma2(acc[i][2], ap, bp2);
                fma2(acc[i][3], ap, bp3);
            }
        }
        __syncthreads();
        if (t + 1 < numT) store_smem();
        __syncthreads();
    }

    // epilogue
    const float* ad = ADDEND ? (addend + (long)bz * (long)M * N) : nullptr;
#pragma unroll
    for (int i = 0; i < 8; i++) {
        int  row  = row0 + ty * 8 + i;
        float bv  = BIAS ? __ldg(&bias[row]) : 0.0f;
        long base = (long)row * N + col0 + tx * 8;
#pragma unroll
        for (int j = 0; j < 4; j++) {
            U64F2 cv; cv.u = acc[i][j];
            float r0 = cv.f.x + bv;
            float r1 = cv.f.y + bv;
            if (ADDEND) {
                r0 += ad[base + 2 * j];
                r1 += ad[base + 2 * j + 1];
            }
            float2 o; o.x = r0; o.y = r1;
            *(float2*)&Cb[base + 2 * j] = o;
        }
    }
}

// ---------------------------------------------------------------------------
// Row softmax over last axis (length 1024). One block per (b, c) row.
// ---------------------------------------------------------------------------
__global__ void row_softmax_kernel(float* __restrict__ data)
{
    long row = blockIdx.x;
    float4* p = reinterpret_cast<float4*>(data + row * 1024);
    int t = threadIdx.x;               // 256 threads, 4 floats each

    float4 v = p[t];
    float m = fmaxf(fmaxf(v.x, v.y), fmaxf(v.z, v.w));

    __shared__ float red[256];
    red[t] = m;
    __syncthreads();
    for (int s = 128; s > 0; s >>= 1) {
        if (t < s) red[t] = fmaxf(red[t], red[t + s]);
        __syncthreads();
    }
    m = red[0];
    __syncthreads();

    float4 e;
    e.x = __expf(v.x - m); e.y = __expf(v.y - m);
    e.z = __expf(v.z - m); e.w = __expf(v.w - m);
    float s4 = e.x + e.y + e.z + e.w;

    red[t] = s4;
    __syncthreads();
    for (int s = 128; s > 0; s >>= 1) {
        if (t < s) red[t] += red[t + s];
        __syncthreads();
    }
    float inv = 1.0f / red[0];

    e.x *= inv; e.y *= inv; e.z *= inv; e.w *= inv;
    p[t] = e;
}

// ---------------------------------------------------------------------------
// Column softmax over channel axis (stride 1024 floats, length 1024).
// block (32 n-lanes, 8 c-parallel); grid (n-tiles=32, batch=32).
// ---------------------------------------------------------------------------
__global__ void col_softmax_kernel(float* __restrict__ data)
{
    const int b  = blockIdx.y;
    const int tx = threadIdx.x;                    // 0..31
    const int ty = threadIdx.y;                    // 0..7
    const int n  = blockIdx.x * 32 + tx;
    float* base = data + (long)b * ELEM_PER_B + n;

    __shared__ float red[8][32];

    float m = -1e30f;
    for (int c = ty; c < 1024; c += 8)
        m = fmaxf(m, base[(long)c << 10]);
    red[ty][tx] = m;
    __syncthreads();
    m = -1e30f;
#pragma unroll
    for (int j = 0; j < 8; j++) m = fmaxf(m, red[j][tx]);
    __syncthreads();

    float s = 0.0f;
    for (int c = ty; c < 1024; c += 8)
        s += __expf(base[(long)c << 10] - m);
    red[ty][tx] = s;
    __syncthreads();
    s = 0.0f;
#pragma unroll
    for (int j = 0; j < 8; j++) s += red[j][tx];
    float inv = 1.0f / s;

    for (int c = ty; c < 1024; c += 8) {
        long idx = (long)c << 10;
        base[idx] = __expf(base[idx] - m) * inv;
    }
}

// ---------------------------------------------------------------------------
// Launch
// ---------------------------------------------------------------------------
extern "C" void kernel_launch(void* const* d_in, const int* in_sizes, int n_in,
                              void* d_out, int out_size)
{
    (void)in_sizes; (void)n_in; (void)out_size;

    const float* x  = (const float*)d_in[0];   // [32, 2048, 32, 32]
    const float* wr = (const float*)d_in[1];   // [1024, 2048]
    const float* br = (const float*)d_in[2];   // [1024]
    const float* wc = (const float*)d_in[3];   // [1024, 1024]
    const float* bc = (const float*)d_in[4];   // [1024]
    const float* wd = (const float*)d_in[5];   // [1024, 1024]
    const float* bd = (const float*)d_in[6];   // [1024]
    float* out = (float*)d_out;                // [32, 1024, 32, 32]

    float *y1, *cbuf, *dbuf;
    cudaGetSymbolAddress((void**)&y1,   g_Y1);
    cudaGetSymbolAddress((void**)&cbuf, g_C);
    cudaGetSymbolAddress((void**)&dbuf, g_D);

    dim3 blk(256), g(8, 8, NB);

    // Y1 = Wr @ X_b + br     (K = 2048, B is [K,N] per batch)
    gemm_f32<false, true, false><<<g, blk>>>(
        wr, 0L, x, (long)2048 * 1024, br, nullptr, y1, MM, NN, 2048);

    // C = Wc @ Y1 + bc
    gemm_f32<false, true, false><<<g, blk>>>(
        wc, 0L, y1, (long)ELEM_PER_B, bc, nullptr, cbuf, MM, NN, 1024);

    // D = Wd @ Y1 + bd
    gemm_f32<false, true, false><<<g, blk>>>(
        wd, 0L, y1, (long)ELEM_PER_B, bd, nullptr, dbuf, MM, NN, 1024);

    // softmaxes
    row_softmax_kernel<<<NB * 1024, 256>>>(cbuf);
    col_softmax_kernel<<<dim3(32, NB), dim3(32, 8)>>>(dbuf);

    // out = Y1 + C @ D^T     (both per batch; TRANSB)
    gemm_f32<true, false, true><<<g, blk>>>(
        cbuf, (long)ELEM_PER_B, dbuf, (long)ELEM_PER_B,
        nullptr, y1, out, MM, NN, 1024);
}

// round 9
// speedup vs baseline: 4.0844x; 4.0760x over previous
#include <cuda_runtime.h>
#include <cuda_bf16.h>
#include <cstdint>

// ---------------------------------------------------------------------------
// PSAttention (B=32, CIN=2048, COUT=HW=1024) via mma.sync bf16 (HMMA.16816).
//   Y1 = Wr @ X_b + br         (bf16x3 split: precision-critical)
//   C  = softmax_rows(Wc @ Y1 + bc)   (single bf16 pass)
//   D  = softmax_cols(Wd @ Y1 + bd)   (single bf16 pass)
//   out = Y1 + C @ D^T                (single bf16 pass; att term is ~1e-3 of out)
// ---------------------------------------------------------------------------

#define NB 32
#define ELEMS (1024 * 1024)

// ---- scratch (device globals; no cudaMalloc allowed) ----------------------
__device__ float          g_Y1 [NB * ELEMS];
__device__ float          g_C  [NB * ELEMS];
__device__ float          g_D  [NB * ELEMS];
__device__ __nv_bfloat16  g_Y1hT[NB * ELEMS];        // Y1^T bf16 (B for GEMM2/3)
__device__ __nv_bfloat16  g_XhT[NB * 1024 * 2048];   // X^T splits (B for GEMM1)
__device__ __nv_bfloat16  g_XlT[NB * 1024 * 2048];
__device__ __nv_bfloat16  g_Ch [NB * ELEMS];
__device__ __nv_bfloat16  g_Dh [NB * ELEMS];
__device__ __nv_bfloat16  g_Wrh[1024 * 2048];
__device__ __nv_bfloat16  g_Wrl[1024 * 2048];
__device__ __nv_bfloat16  g_Wch[1024 * 1024];
__device__ __nv_bfloat16  g_Wdh[1024 * 1024];

// ---------------------------------------------------------------------------
// helpers
// ---------------------------------------------------------------------------
__device__ __forceinline__ uint32_t smem_u32(const void* p) {
    uint32_t a;
    asm("{ .reg .u64 t; cvta.to.shared.u64 t, %1; cvt.u32.u64 %0, t; }" : "=r"(a) : "l"(p));
    return a;
}
#define CP16(dst, src) \
    asm volatile("cp.async.cg.shared.global [%0], [%1], 16;" :: "r"(dst), "l"(src))

__device__ __forceinline__ uint32_t swz(uint32_t off) {
    return off ^ ((off >> 3) & 0x70);
}
__device__ __forceinline__ void ldsm4(uint32_t* r, uint32_t a) {
    asm volatile("ldmatrix.sync.aligned.m8n8.x4.shared.b16 {%0,%1,%2,%3}, [%4];"
        : "=r"(r[0]), "=r"(r[1]), "=r"(r[2]), "=r"(r[3]) : "r"(a));
}
__device__ __forceinline__ void ldsm2(uint32_t* r, uint32_t a) {
    asm volatile("ldmatrix.sync.aligned.m8n8.x2.shared.b16 {%0,%1}, [%2];"
        : "=r"(r[0]), "=r"(r[1]) : "r"(a));
}
__device__ __forceinline__ void mma16816(float* c, const uint32_t* a, const uint32_t* b) {
    asm volatile("mma.sync.aligned.m16n8k16.row.col.f32.bf16.bf16.f32 "
        "{%0,%1,%2,%3},{%4,%5,%6,%7},{%8,%9},{%0,%1,%2,%3};"
        : "+f"(c[0]), "+f"(c[1]), "+f"(c[2]), "+f"(c[3])
        : "r"(a[0]), "r"(a[1]), "r"(a[2]), "r"(a[3]), "r"(b[0]), "r"(b[1]));
}
__device__ __forceinline__ void split2(float v, __nv_bfloat16& h, __nv_bfloat16& l) {
    h = __float2bfloat16(v);
    l = __float2bfloat16(v - __bfloat162float(h));
}

// ---------------------------------------------------------------------------
// stage loader: CTA tile A[128 x 64] (+Al) and B[128 x 64] (+Bl), K-major,
// 128B rows, SW128 swizzle, 16B cp.async.  1 commit group per stage.
// ---------------------------------------------------------------------------
template<int SPLIT>
__device__ __forceinline__ void load_stage(
    uint32_t sb, int s, int m0, int n0, int K, int ks0,
    const __nv_bfloat16* Ah, const __nv_bfloat16* Al,
    const __nv_bfloat16* Bh, const __nv_bfloat16* Bl, int tid)
{
    const uint32_t STAGE = (SPLIT == 3) ? 65536u : 32768u;
    const uint32_t bOff  = (SPLIT == 3) ? 32768u : 16384u;
    uint32_t buf = sb + (uint32_t)(s % 3) * STAGE;
#pragma unroll
    for (int i = 0; i < 4; i++) {
        int idx = tid + (i << 8);
        int r = idx >> 3, c = idx & 7;
        long goff = (long)r * K + ks0 + (c << 3);
        uint32_t sw = swz((uint32_t)(r * 128 + c * 16));
        CP16(buf + sw, Ah + (long)m0 * K + goff);
        CP16(buf + bOff + sw, Bh + (long)n0 * K + goff);
        if (SPLIT == 3) {
            CP16(buf + 16384u + sw, Al + (long)m0 * K + goff);
            CP16(buf + 49152u + sw, Bl + (long)n0 * K + goff);
        }
    }
    asm volatile("cp.async.commit_group;" ::: "memory");
}

// ---------------------------------------------------------------------------
// GEMM: out[1024,1024] (per batch) = A[M,K] * B[N,K]^T, A/B K-major bf16.
// MODE 0: +bias, write fp32 outF and transposed bf16 outHT
// MODE 1: +bias, write fp32 outF
// MODE 2: +addend, write fp32 outF
// CTA 128x128, 8 warps = 2(m) x 4(n), warp tile 64x32. 3-stage cp.async.
// ---------------------------------------------------------------------------
template<int SPLIT, int MODE>
__global__ __launch_bounds__(256, 1)
void gemm_mma(const __nv_bfloat16* __restrict__ Ah_, const __nv_bfloat16* __restrict__ Al_,
              long strideA,
              const __nv_bfloat16* __restrict__ Bh_, const __nv_bfloat16* __restrict__ Bl_,
              long strideB, int K,
              const float* __restrict__ bias,
              float* __restrict__ outF,
              const float* __restrict__ addend,
              __nv_bfloat16* __restrict__ outHT)
{
    extern __shared__ char smraw[];
    uint32_t sb = (smem_u32(smraw) + 1023u) & ~1023u;
    const int tid = threadIdx.x, lane = tid & 31, wid = tid >> 5;
    const int bz = blockIdx.z;
    const int m0 = blockIdx.y * 128, n0 = blockIdx.x * 128;

    const __nv_bfloat16* Ah = Ah_ + (long)bz * strideA;
    const __nv_bfloat16* Al = (SPLIT == 3) ? (Al_ + (long)bz * strideA) : nullptr;
    const __nv_bfloat16* Bh = Bh_ + (long)bz * strideB;
    const __nv_bfloat16* Bl = (SPLIT == 3) ? (Bl_ + (long)bz * strideB) : nullptr;

    const int wm0 = (wid & 1) * 64;     // warp m offset in CTA tile
    const int wn0 = (wid >> 1) * 32;    // warp n offset

    float acc[4][4][4];
#pragma unroll
    for (int a = 0; a < 4; a++)
#pragma unroll
        for (int b = 0; b < 4; b++)
#pragma unroll
            for (int c = 0; c < 4; c++) acc[a][b][c] = 0.0f;

    const int nC = K >> 6;
    load_stage<SPLIT>(sb, 0, m0, n0, K, 0,  Ah, Al, Bh, Bl, tid);
    load_stage<SPLIT>(sb, 1, m0, n0, K, 64, Ah, Al, Bh, Bl, tid);

    const uint32_t STAGE = (SPLIT == 3) ? 65536u : 32768u;
    const uint32_t bOff  = (SPLIT == 3) ? 32768u : 16384u;

    for (int s = 0; s < nC; s++) {
        if (s == nC - 1) asm volatile("cp.async.wait_group 0;" ::: "memory");
        else             asm volatile("cp.async.wait_group 1;" ::: "memory");
        __syncthreads();

        uint32_t buf = sb + (uint32_t)(s % 3) * STAGE;
        uint32_t aB = buf, alB = buf + 16384u;
        uint32_t bB = buf + bOff, blB = bB + 16384u;

#pragma unroll
        for (int ks = 0; ks < 4; ks++) {
            uint32_t ah[4][4], al[4][4], bh[4][2], bl[4][2];
            const int      arow = wm0 + (lane & 15);
            const uint32_t akb  = (uint32_t)(ks * 32 + (lane >> 4) * 16);
#pragma unroll
            for (int mt = 0; mt < 4; mt++) {
                uint32_t off = (uint32_t)((arow + mt * 16) * 128) + akb;
                uint32_t sw = swz(off);
                ldsm4(ah[mt], aB + sw);
                if (SPLIT == 3) ldsm4(al[mt], alB + sw);
            }
            const int      brow = wn0 + (lane & 7);
            const uint32_t bkb  = (uint32_t)(ks * 32 + ((lane >> 3) & 1) * 16);
#pragma unroll
            for (int nt = 0; nt < 4; nt++) {
                uint32_t off = (uint32_t)((brow + nt * 8) * 128) + bkb;
                uint32_t sw = swz(off);
                ldsm2(bh[nt], bB + sw);
                if (SPLIT == 3) ldsm2(bl[nt], blB + sw);
            }
#pragma unroll
            for (int mt = 0; mt < 4; mt++)
#pragma unroll
                for (int nt = 0; nt < 4; nt++) {
                    mma16816(acc[mt][nt], ah[mt], bh[nt]);
                    if (SPLIT == 3) {
                        mma16816(acc[mt][nt], ah[mt], bl[nt]);
                        mma16816(acc[mt][nt], al[mt], bh[nt]);
                    }
                }
        }
        if (s + 2 < nC)
            load_stage<SPLIT>(sb, s + 2, m0, n0, K, (s + 2) << 6, Ah, Al, Bh, Bl, tid);
    }

    // ---- epilogue --------------------------------------------------------
    const long ob = (long)bz << 20;
#pragma unroll
    for (int mt = 0; mt < 4; mt++) {
        const int r0 = m0 + wm0 + mt * 16 + (lane >> 2);
        float b0 = 0.0f, b1 = 0.0f;
        if (MODE == 0 || MODE == 1) { b0 = __ldg(&bias[r0]); b1 = __ldg(&bias[r0 + 8]); }
#pragma unroll
        for (int nt = 0; nt < 4; nt++) {
            const int col = n0 + wn0 + nt * 8 + (lane & 3) * 2;
            float v0 = acc[mt][nt][0] + b0, v1 = acc[mt][nt][1] + b0;
            float v2 = acc[mt][nt][2] + b1, v3 = acc[mt][nt][3] + b1;
            const long i0 = ob + (long)r0 * 1024 + col;
            const long i1 = ob + (long)(r0 + 8) * 1024 + col;
            if (MODE == 2) {
                float2 a0 = *(const float2*)(addend + i0);
                float2 a1 = *(const float2*)(addend + i1);
                v0 += a0.x; v1 += a0.y; v2 += a1.x; v3 += a1.y;
            }
            *(float2*)(outF + i0) = make_float2(v0, v1);
            *(float2*)(outF + i1) = make_float2(v2, v3);
            if (MODE == 0) {
                outHT[ob + (long)col * 1024 + r0]           = __float2bfloat16(v0);
                outHT[ob + (long)(col + 1) * 1024 + r0]     = __float2bfloat16(v1);
                outHT[ob + (long)col * 1024 + r0 + 8]       = __float2bfloat16(v2);
                outHT[ob + (long)(col + 1) * 1024 + r0 + 8] = __float2bfloat16(v3);
            }
        }
    }
}

// ---------------------------------------------------------------------------
// conversions
// ---------------------------------------------------------------------------
__global__ void split_x_T(const float* __restrict__ X,
                          __nv_bfloat16* __restrict__ oh,
                          __nv_bfloat16* __restrict__ ol)
{
    __shared__ float tile[32][33];
    const int b = blockIdx.z;
    const int c0 = blockIdx.y * 32, n0 = blockIdx.x * 32;
    const int tx = threadIdx.x, ty = threadIdx.y;        // (32, 8)
    const float* src = X + ((long)b * 2048 + c0) * 1024 + n0;
#pragma unroll
    for (int i = 0; i < 4; i++)
        tile[ty + 8 * i][tx] = src[(long)(ty + 8 * i) * 1024 + tx];
    __syncthreads();
    const long obase = ((long)b * 1024 + n0) * 2048 + c0;
#pragma unroll
    for (int i = 0; i < 4; i++) {
        __nv_bfloat16 h, l;
        split2(tile[tx][ty + 8 * i], h, l);
        long o = obase + (long)(ty + 8 * i) * 2048 + tx;
        oh[o] = h; ol[o] = l;
    }
}

__global__ void split_w3(const float* __restrict__ w,
                         __nv_bfloat16* __restrict__ h,
                         __nv_bfloat16* __restrict__ l, int n)
{
    int i = blockIdx.x * 256 + threadIdx.x;
    if (i < n) { __nv_bfloat16 a, b; split2(w[i], a, b); h[i] = a; l[i] = b; }
}
__global__ void conv_h(const float* __restrict__ w,
                       __nv_bfloat16* __restrict__ h, int n)
{
    int i = blockIdx.x * 256 + threadIdx.x;
    if (i < n) h[i] = __float2bfloat16(w[i]);
}

// ---------------------------------------------------------------------------
// softmaxes -> bf16
// ---------------------------------------------------------------------------
__global__ void row_softmax_h(const float* __restrict__ in,
                              __nv_bfloat16* __restrict__ oh)
{
    const long rowb = (long)blockIdx.x * 1024;
    const float4* p = (const float4*)(in + rowb);
    const int t = threadIdx.x;      // 256 threads x 4

    float4 v = p[t];
    float m = fmaxf(fmaxf(v.x, v.y), fmaxf(v.z, v.w));
    __shared__ float red[256];
    red[t] = m; __syncthreads();
    for (int s = 128; s > 0; s >>= 1) { if (t < s) red[t] = fmaxf(red[t], red[t + s]); __syncthreads(); }
    m = red[0]; __syncthreads();

    float e0 = __expf(v.x - m), e1 = __expf(v.y - m);
    float e2 = __expf(v.z - m), e3 = __expf(v.w - m);
    red[t] = e0 + e1 + e2 + e3; __syncthreads();
    for (int s = 128; s > 0; s >>= 1) { if (t < s) red[t] += red[t + s]; __syncthreads(); }
    const float inv = 1.0f / red[0];

    __nv_bfloat162 o01, o23;
    o01.x = __float2bfloat16(e0 * inv); o01.y = __float2bfloat16(e1 * inv);
    o23.x = __float2bfloat16(e2 * inv); o23.y = __float2bfloat16(e3 * inv);
    __nv_bfloat162* ph = (__nv_bfloat162*)(oh + rowb + t * 4);
    ph[0] = o01; ph[1] = o23;
}

__global__ void col_softmax_h(const float* __restrict__ in,
                              __nv_bfloat16* __restrict__ oh)
{
    const int b = blockIdx.y;
    const int tx = threadIdx.x, ty = threadIdx.y;   // (32, 8)
    const int n = blockIdx.x * 32 + tx;
    const long base = (long)b * ELEMS + n;

    __shared__ float red[8][32];

    float m = -1e30f;
    for (int c = ty; c < 1024; c += 8) m = fmaxf(m, in[base + ((long)c << 10)]);
    red[ty][tx] = m; __syncthreads();
    m = -1e30f;
#pragma unroll
    for (int j = 0; j < 8; j++) m = fmaxf(m, red[j][tx]);
    __syncthreads();

    float s = 0.0f;
    for (int c = ty; c < 1024; c += 8) s += __expf(in[base + ((long)c << 10)] - m);
    red[ty][tx] = s; __syncthreads();
    s = 0.0f;
#pragma unroll
    for (int j = 0; j < 8; j++) s += red[j][tx];
    const float inv = 1.0f / s;

    for (int c = ty; c < 1024; c += 8) {
        long idx = base + ((long)c << 10);
        oh[idx] = __float2bfloat16(__expf(in[idx] - m) * inv);
    }
}

// ---------------------------------------------------------------------------
// launch
// ---------------------------------------------------------------------------
#define SMEM3 (3 * 65536 + 1024)
#define SMEM1 (3 * 32768 + 1024)

extern "C" void kernel_launch(void* const* d_in, const int* in_sizes, int n_in,
                              void* d_out, int out_size)
{
    (void)in_sizes; (void)n_in; (void)out_size;

    const float* x  = (const float*)d_in[0];
    const float* wr = (const float*)d_in[1];
    const float* br = (const float*)d_in[2];
    const float* wc = (const float*)d_in[3];
    const float* bc = (const float*)d_in[4];
    const float* wd = (const float*)d_in[5];
    const float* bd = (const float*)d_in[6];
    float* out = (float*)d_out;

    float *y1, *cbuf, *dbuf;
    __nv_bfloat16 *y1hT, *xhT, *xlT, *ch, *dh, *wrh, *wrl, *wch, *wdh;
    cudaGetSymbolAddress((void**)&y1,   g_Y1);
    cudaGetSymbolAddress((void**)&cbuf, g_C);
    cudaGetSymbolAddress((void**)&dbuf, g_D);
    cudaGetSymbolAddress((void**)&y1hT, g_Y1hT);
    cudaGetSymbolAddress((void**)&xhT,  g_XhT);
    cudaGetSymbolAddress((void**)&xlT,  g_XlT);
    cudaGetSymbolAddress((void**)&ch,   g_Ch);
    cudaGetSymbolAddress((void**)&dh,   g_Dh);
    cudaGetSymbolAddress((void**)&wrh,  g_Wrh);
    cudaGetSymbolAddress((void**)&wrl,  g_Wrl);
    cudaGetSymbolAddress((void**)&wch,  g_Wch);
    cudaGetSymbolAddress((void**)&wdh,  g_Wdh);

    cudaFuncSetAttribute((const void*)gemm_mma<3, 0>, cudaFuncAttributeMaxDynamicSharedMemorySize, SMEM3);
    cudaFuncSetAttribute((const void*)gemm_mma<1, 1>, cudaFuncAttributeMaxDynamicSharedMemorySize, SMEM1);
    cudaFuncSetAttribute((const void*)gemm_mma<1, 2>, cudaFuncAttributeMaxDynamicSharedMemorySize, SMEM1);

    // conversions
    split_w3<<<(2 * 1024 * 1024) / 256, 256>>>(wr, wrh, wrl, 2 * 1024 * 1024);
    conv_h<<<(1024 * 1024) / 256, 256>>>(wc, wch, 1024 * 1024);
    conv_h<<<(1024 * 1024) / 256, 256>>>(wd, wdh, 1024 * 1024);
    split_x_T<<<dim3(32, 64, NB), dim3(32, 8)>>>(x, xhT, xlT);

    dim3 g(8, 8, NB), blk(256);

    // GEMM1 (split x3): Y1 = Wr @ X + br ; emits Y1 fp32 + Y1^T bf16
    gemm_mma<3, 0><<<g, blk, SMEM3>>>(wrh, wrl, 0L, xhT, xlT, (long)1024 * 2048,
                                      2048, br, y1, nullptr, y1hT);
    // GEMM2: C = Wc @ Y1 + bc
    gemm_mma<1, 1><<<g, blk, SMEM1>>>(wch, nullptr, 0L, y1hT, nullptr, (long)ELEMS,
                                      1024, bc, cbuf, nullptr, nullptr);
    // GEMM3: D = Wd @ Y1 + bd
    gemm_mma<1, 1><<<g, blk, SMEM1>>>(wdh, nullptr, 0L, y1hT, nullptr, (long)ELEMS,
                                      1024, bd, dbuf, nullptr, nullptr);

    row_softmax_h<<<NB * 1024, 256>>>(cbuf, ch);
    col_softmax_h<<<dim3(32, NB), dim3(32, 8)>>>(dbuf, dh);

    // GEMM4: out = Y1 + C @ D^T
    gemm_mma<1, 2><<<g, blk, SMEM1>>>(ch, nullptr, (long)ELEMS, dh, nullptr, (long)ELEMS,
                                      1024, nullptr, out, y1, nullptr);
}

// round 10
// speedup vs baseline: 6.4653x; 1.5829x over previous
#include <cuda_runtime.h>
#include <cuda_fp16.h>
#include <cstdint>

// ---------------------------------------------------------------------------
// PSAttention (B=32, CIN=2048, COUT=HW=1024) via single-pass fp16 HMMA.16816.
//   Y1 = Wr @ X_b + br
//   C  = softmax_rows(Wc @ Y1 + bc)
//   D  = softmax_cols(Wd @ Y1 + bd)
//   out = Y1 + C @ D^T
// fp16 operand rounding gives ~2e-4 aggregate rel err (threshold 1e-3).
// ---------------------------------------------------------------------------

#define NB 32
#define ELEMS (1024 * 1024)

__device__ float   g_Y1 [NB * ELEMS];            // fp32 Y1 (residual add + accuracy)
__device__ float   g_C  [NB * ELEMS];
__device__ float   g_D  [NB * ELEMS];
__device__ __half  g_Y1T[NB * ELEMS];            // Y1^T fp16 (B for GEMM2/3)
__device__ __half  g_XT [NB * 1024 * 2048];      // X^T fp16  (B for GEMM1)
__device__ __half  g_Ch [NB * ELEMS];
__device__ __half  g_Dh [NB * ELEMS];
__device__ __half  g_Wr [1024 * 2048];
__device__ __half  g_Wc [1024 * 1024];
__device__ __half  g_Wd [1024 * 1024];

// ---------------------------------------------------------------------------
// helpers
// ---------------------------------------------------------------------------
__device__ __forceinline__ uint32_t smem_u32(const void* p) {
    uint32_t a;
    asm("{ .reg .u64 t; cvta.to.shared.u64 t, %1; cvt.u32.u64 %0, t; }" : "=r"(a) : "l"(p));
    return a;
}
#define CP16(dst, src) \
    asm volatile("cp.async.cg.shared.global [%0], [%1], 16;" :: "r"(dst), "l"(src))

__device__ __forceinline__ uint32_t swz(uint32_t off) {
    return off ^ ((off >> 3) & 0x70);
}
__device__ __forceinline__ void ldsm4(uint32_t* r, uint32_t a) {
    asm volatile("ldmatrix.sync.aligned.m8n8.x4.shared.b16 {%0,%1,%2,%3}, [%4];"
        : "=r"(r[0]), "=r"(r[1]), "=r"(r[2]), "=r"(r[3]) : "r"(a));
}
__device__ __forceinline__ void mma16816(float* c, const uint32_t* a, const uint32_t* b) {
    asm volatile("mma.sync.aligned.m16n8k16.row.col.f32.f16.f16.f32 "
        "{%0,%1,%2,%3},{%4,%5,%6,%7},{%8,%9},{%0,%1,%2,%3};"
        : "+f"(c[0]), "+f"(c[1]), "+f"(c[2]), "+f"(c[3])
        : "r"(a[0]), "r"(a[1]), "r"(a[2]), "r"(a[3]), "r"(b[0]), "r"(b[1]));
}

// ---------------------------------------------------------------------------
// stage loader: A[128 x 64] + B[256 x 64] fp16 K-major, SW128, 16B cp.async.
// stage = 48KB (A 16KB @ +0, B 32KB @ +16384).
// ---------------------------------------------------------------------------
#define STAGE 49152u
__device__ __forceinline__ void load_stage(
    uint32_t sb, int s, int m0, int n0, int K, int ks0,
    const __half* A, const __half* B, int tid)
{
    uint32_t buf = sb + (uint32_t)(s % 3) * STAGE;
#pragma unroll
    for (int i = 0; i < 4; i++) {          // A: 128 rows x 8 chunks
        int idx = tid + (i << 8);
        int r = idx >> 3, c = idx & 7;
        uint32_t sw = swz((uint32_t)(r * 128 + c * 16));
        CP16(buf + sw, A + (long)(m0 + r) * K + ks0 + (c << 3));
    }
#pragma unroll
    for (int i = 0; i < 8; i++) {          // B: 256 rows x 8 chunks
        int idx = tid + (i << 8);
        int r = idx >> 3, c = idx & 7;
        uint32_t sw = swz((uint32_t)(r * 128 + c * 16));
        CP16(buf + 16384u + sw, B + (long)(n0 + r) * K + ks0 + (c << 3));
    }
    asm volatile("cp.async.commit_group;" ::: "memory");
}

// ---------------------------------------------------------------------------
// GEMM: out[1024,1024] per batch = A[M,K] * B[N,K]^T (K-major fp16 operands).
// MODE 0: +bias, write fp32 outF + transposed fp16 outHT
// MODE 1: +bias, write fp32 outF
// MODE 2: +addend, write fp32 outF
// CTA 128x256, 8 warps = 2(m) x 4(n), warp tile 64x64. 3-stage cp.async.
// ---------------------------------------------------------------------------
template<int MODE>
__global__ __launch_bounds__(256, 1)
void gemm_mma(const __half* __restrict__ A_, long strideA,
              const __half* __restrict__ B_, long strideB, int K,
              const float* __restrict__ bias,
              float* __restrict__ outF,
              const float* __restrict__ addend,
              __half* __restrict__ outHT)
{
    extern __shared__ char smraw[];
    uint32_t sb = (smem_u32(smraw) + 1023u) & ~1023u;
    const int tid = threadIdx.x, lane = tid & 31, wid = tid >> 5;
    const int bz = blockIdx.z;
    const int m0 = blockIdx.y * 128, n0 = blockIdx.x * 256;

    const __half* A = A_ + (long)bz * strideA;
    const __half* B = B_ + (long)bz * strideB;

    const int wm0 = (wid & 1) * 64;      // warp m offset
    const int wn0 = (wid >> 1) * 64;     // warp n offset

    float acc[4][8][4];
#pragma unroll
    for (int a = 0; a < 4; a++)
#pragma unroll
        for (int b = 0; b < 8; b++)
#pragma unroll
            for (int c = 0; c < 4; c++) acc[a][b][c] = 0.0f;

    const int nC = K >> 6;
    load_stage(sb, 0, m0, n0, K, 0,  A, B, tid);
    load_stage(sb, 1, m0, n0, K, 64, A, B, tid);

    // lane-dependent ldmatrix address components (constant across stages)
    const int      arow = wm0 + (lane & 15);
    const uint32_t akb0 = (uint32_t)((lane >> 4) * 16);
    const int      brow = wn0 + (lane & 7) + ((lane >> 4) << 3);
    const uint32_t bkb0 = (uint32_t)(((lane >> 3) & 1) * 16);

    for (int s = 0; s < nC; s++) {
        if (s == nC - 1) asm volatile("cp.async.wait_group 0;" ::: "memory");
        else             asm volatile("cp.async.wait_group 1;" ::: "memory");
        __syncthreads();

        uint32_t aB = sb + (uint32_t)(s % 3) * STAGE;
        uint32_t bB = aB + 16384u;

#pragma unroll
        for (int ks = 0; ks < 4; ks++) {
            uint32_t ah[4][4], bb[4][4];
            const uint32_t akb = (uint32_t)(ks * 32) + akb0;
            const uint32_t bkb = (uint32_t)(ks * 32) + bkb0;
#pragma unroll
            for (int mt = 0; mt < 4; mt++)
                ldsm4(ah[mt], aB + swz((uint32_t)((arow + mt * 16) * 128) + akb));
#pragma unroll
            for (int q = 0; q < 4; q++)    // each covers two n8 fragments
                ldsm4(bb[q], bB + swz((uint32_t)((brow + q * 16) * 128) + bkb));
#pragma unroll
            for (int mt = 0; mt < 4; mt++)
#pragma unroll
                for (int nb = 0; nb < 8; nb++)
                    mma16816(acc[mt][nb], ah[mt], &bb[nb >> 1][(nb & 1) * 2]);
        }
        if (s + 2 < nC)
            load_stage(sb, s + 2, m0, n0, K, (s + 2) << 6, A, B, tid);
    }

    // ---- epilogue ---------------------------------------------------------
    const long ob = (long)bz << 20;
#pragma unroll
    for (int mt = 0; mt < 4; mt++) {
        const int r0 = m0 + wm0 + mt * 16 + (lane >> 2);
        float b0 = 0.0f, b1 = 0.0f;
        if (MODE == 0 || MODE == 1) { b0 = __ldg(&bias[r0]); b1 = __ldg(&bias[r0 + 8]); }
#pragma unroll
        for (int nb = 0; nb < 8; nb++) {
            const int col = n0 + wn0 + nb * 8 + (lane & 3) * 2;
            float v0 = acc[mt][nb][0] + b0, v1 = acc[mt][nb][1] + b0;
            float v2 = acc[mt][nb][2] + b1, v3 = acc[mt][nb][3] + b1;
            const long i0 = ob + (long)r0 * 1024 + col;
            const long i1 = ob + (long)(r0 + 8) * 1024 + col;
            if (MODE == 2) {
                float2 a0 = *(const float2*)(addend + i0);
                float2 a1 = *(const float2*)(addend + i1);
                v0 += a0.x; v1 += a0.y; v2 += a1.x; v3 += a1.y;
            }
            *(float2*)(outF + i0) = make_float2(v0, v1);
            *(float2*)(outF + i1) = make_float2(v2, v3);
            if (MODE == 0) {
                outHT[ob + (long)col * 1024 + r0]           = __float2half(v0);
                outHT[ob + (long)(col + 1) * 1024 + r0]     = __float2half(v1);
                outHT[ob + (long)col * 1024 + r0 + 8]       = __float2half(v2);
                outHT[ob + (long)(col + 1) * 1024 + r0 + 8] = __float2half(v3);
            }
        }
    }
}

// ---------------------------------------------------------------------------
// conversions
// ---------------------------------------------------------------------------
__global__ void conv_x_T(const float* __restrict__ X, __half* __restrict__ o)
{
    __shared__ float tile[32][33];
    const int b = blockIdx.z;
    const int c0 = blockIdx.y * 32, n0 = blockIdx.x * 32;
    const int tx = threadIdx.x, ty = threadIdx.y;     // (32, 8)
    const float* src = X + ((long)b * 2048 + c0) * 1024 + n0;
#pragma unroll
    for (int i = 0; i < 4; i++)
        tile[ty + 8 * i][tx] = src[(long)(ty + 8 * i) * 1024 + tx];
    __syncthreads();
    const long obase = ((long)b * 1024 + n0) * 2048 + c0;
#pragma unroll
    for (int i = 0; i < 4; i++)
        o[obase + (long)(ty + 8 * i) * 2048 + tx] = __float2half(tile[tx][ty + 8 * i]);
}

__global__ void conv_h(const float* __restrict__ w, __half* __restrict__ h, int n)
{
    int i = blockIdx.x * 256 + threadIdx.x;
    if (i < n) h[i] = __float2half(w[i]);
}

// ---------------------------------------------------------------------------
// softmaxes -> fp16
// ---------------------------------------------------------------------------
__global__ void row_softmax_h(const float* __restrict__ in, __half* __restrict__ oh)
{
    const long rowb = (long)blockIdx.x * 1024;
    const float4* p = (const float4*)(in + rowb);
    const int t = threadIdx.x;            // 256 threads x 4

    float4 v = p[t];
    float m = fmaxf(fmaxf(v.x, v.y), fmaxf(v.z, v.w));
    __shared__ float red[256];
    red[t] = m; __syncthreads();
    for (int s = 128; s > 0; s >>= 1) { if (t < s) red[t] = fmaxf(red[t], red[t + s]); __syncthreads(); }
    m = red[0]; __syncthreads();

    float e0 = __expf(v.x - m), e1 = __expf(v.y - m);
    float e2 = __expf(v.z - m), e3 = __expf(v.w - m);
    red[t] = e0 + e1 + e2 + e3; __syncthreads();
    for (int s = 128; s > 0; s >>= 1) { if (t < s) red[t] += red[t + s]; __syncthreads(); }
    const float inv = 1.0f / red[0];

    __half2* ph = (__half2*)(oh + rowb + t * 4);
    ph[0] = __floats2half2_rn(e0 * inv, e1 * inv);
    ph[1] = __floats2half2_rn(e2 * inv, e3 * inv);
}

__global__ void col_softmax_h(const float* __restrict__ in, __half* __restrict__ oh)
{
    const int b = blockIdx.y;
    const int tx = threadIdx.x, ty = threadIdx.y;      // (32, 8)
    const int n = blockIdx.x * 32 + tx;
    const long base = (long)b * ELEMS + n;

    __shared__ float red[8][32];

    float m = -1e30f;
    for (int c = ty; c < 1024; c += 8) m = fmaxf(m, in[base + ((long)c << 10)]);
    red[ty][tx] = m; __syncthreads();
    m = -1e30f;
#pragma unroll
    for (int j = 0; j < 8; j++) m = fmaxf(m, red[j][tx]);
    __syncthreads();

    float s = 0.0f;
    for (int c = ty; c < 1024; c += 8) s += __expf(in[base + ((long)c << 10)] - m);
    red[ty][tx] = s; __syncthreads();
    s = 0.0f;
#pragma unroll
    for (int j = 0; j < 8; j++) s += red[j][tx];
    const float inv = 1.0f / s;

    for (int c = ty; c < 1024; c += 8) {
        long idx = base + ((long)c << 10);
        oh[idx] = __float2half(__expf(in[idx] - m) * inv);
    }
}

// ---------------------------------------------------------------------------
// launch
// ---------------------------------------------------------------------------
#define SMEM_DYN (3 * 49152 + 1024)

extern "C" void kernel_launch(void* const* d_in, const int* in_sizes, int n_in,
                              void* d_out, int out_size)
{
    (void)in_sizes; (void)n_in; (void)out_size;

    const float* x  = (const float*)d_in[0];
    const float* wr = (const float*)d_in[1];
    const float* br = (const float*)d_in[2];
    const float* wc = (const float*)d_in[3];
    const float* bc = (const float*)d_in[4];
    const float* wd = (const float*)d_in[5];
    const float* bd = (const float*)d_in[6];
    float* out = (float*)d_out;

    float *y1, *cbuf, *dbuf;
    __half *y1T, *xT, *ch, *dh, *wrh, *wch, *wdh;
    cudaGetSymbolAddress((void**)&y1,   g_Y1);
    cudaGetSymbolAddress((void**)&cbuf, g_C);
    cudaGetSymbolAddress((void**)&dbuf, g_D);
    cudaGetSymbolAddress((void**)&y1T,  g_Y1T);
    cudaGetSymbolAddress((void**)&xT,   g_XT);
    cudaGetSymbolAddress((void**)&ch,   g_Ch);
    cudaGetSymbolAddress((void**)&dh,   g_Dh);
    cudaGetSymbolAddress((void**)&wrh,  g_Wr);
    cudaGetSymbolAddress((void**)&wch,  g_Wc);
    cudaGetSymbolAddress((void**)&wdh,  g_Wd);

    cudaFuncSetAttribute((const void*)gemm_mma<0>, cudaFuncAttributeMaxDynamicSharedMemorySize, SMEM_DYN);
    cudaFuncSetAttribute((const void*)gemm_mma<1>, cudaFuncAttributeMaxDynamicSharedMemorySize, SMEM_DYN);
    cudaFuncSetAttribute((const void*)gemm_mma<2>, cudaFuncAttributeMaxDynamicSharedMemorySize, SMEM_DYN);

    // conversions
    conv_h<<<(2 * 1024 * 1024) / 256, 256>>>(wr, wrh, 2 * 1024 * 1024);
    conv_h<<<(1024 * 1024) / 256, 256>>>(wc, wch, 1024 * 1024);
    conv_h<<<(1024 * 1024) / 256, 256>>>(wd, wdh, 1024 * 1024);
    conv_x_T<<<dim3(32, 64, NB), dim3(32, 8)>>>(x, xT);

    dim3 g(4, 8, NB), blk(256);

    // GEMM1: Y1 = Wr @ X + br ; emits Y1 fp32 + Y1^T fp16
    gemm_mma<0><<<g, blk, SMEM_DYN>>>(wrh, 0L, xT, (long)1024 * 2048,
                                      2048, br, y1, nullptr, y1T);
    // GEMM2: C = Wc @ Y1 + bc
    gemm_mma<1><<<g, blk, SMEM_DYN>>>(wch, 0L, y1T, (long)ELEMS,
                                      1024, bc, cbuf, nullptr, nullptr);
    // GEMM3: D = Wd @ Y1 + bd
    gemm_mma<1><<<g, blk, SMEM_DYN>>>(wdh, 0L, y1T, (long)ELEMS,
                                      1024, bd, dbuf, nullptr, nullptr);

    row_softmax_h<<<NB * 1024, 256>>>(cbuf, ch);
    col_softmax_h<<<dim3(32, NB), dim3(32, 8)>>>(dbuf, dh);

    // GEMM4: out = Y1 + C @ D^T
    gemm_mma<2><<<g, blk, SMEM_DYN>>>(ch, (long)ELEMS, dh, (long)ELEMS,
                                      1024, nullptr, out, y1, nullptr);
}